// round 9
// baseline (speedup 1.0000x reference)
#include <cuda_runtime.h>
#include <cuda_bf16.h>
#include <math.h>

#define N_NODES 100000
#define IN_DIM  128
#define HID     64
#define NCLS    40
#define N_EDGES 1600000
#define CHUNK   512
#define NCHUNK  ((N_NODES + CHUNK - 1) / CHUNK)   // 196

// Scratch (__device__ globals per alloc-free rule)
__device__ float g_A[(size_t)N_NODES * HID];
__device__ float g_B[(size_t)N_NODES * HID];
__device__ int   g_cnt[N_NODES];
__device__ int   g_ptr[N_NODES + 1];
__device__ int   g_partials[NCHUNK];
__device__ int2  g_csr[N_EDGES];

// ---------------------------------------------------------------------------
// tf32 helpers
// ---------------------------------------------------------------------------
__device__ __forceinline__ float to_tf32(float x) {
    unsigned u;
    asm("cvt.rna.tf32.f32 %0, %1;" : "=r"(u) : "f"(x));
    return __uint_as_float(u);
}

__device__ __forceinline__ void mma_tf32(float4& d,
                                         unsigned a0, unsigned a1, unsigned a2, unsigned a3,
                                         unsigned b0, unsigned b1) {
    asm volatile(
        "mma.sync.aligned.m16n8k8.row.col.f32.tf32.tf32.f32 "
        "{%0,%1,%2,%3}, {%4,%5,%6,%7}, {%8,%9}, {%0,%1,%2,%3};"
        : "+f"(d.x), "+f"(d.y), "+f"(d.z), "+f"(d.w)
        : "r"(a0), "r"(a1), "r"(a2), "r"(a3), "r"(b0), "r"(b1));
}

// ---------------------------------------------------------------------------
// CSR construction (R8, unchanged)
// ---------------------------------------------------------------------------
__global__ void zero_int_kernel(int* __restrict__ p, int n) {
    int i = blockIdx.x * blockDim.x + threadIdx.x;
    if (i < n) p[i] = 0;
}

__global__ void hist_kernel(const int* __restrict__ er, int* __restrict__ cnt, int E) {
    int e = blockIdx.x * blockDim.x + threadIdx.x;
    if (e < E) atomicAdd(&cnt[er[e]], 1);
}

__global__ void chunk_reduce_kernel(const int* __restrict__ cnt, int* __restrict__ partials, int N) {
    __shared__ int s[CHUNK];
    int t = threadIdx.x;
    int i = blockIdx.x * CHUNK + t;
    s[t] = (i < N) ? cnt[i] : 0;
    __syncthreads();
    for (int off = CHUNK / 2; off > 0; off >>= 1) {
        if (t < off) s[t] += s[t + off];
        __syncthreads();
    }
    if (t == 0) partials[blockIdx.x] = s[0];
}

__global__ void block_scan_kernel(const int* __restrict__ cnt,
                                  const int* __restrict__ partials,
                                  int* __restrict__ ptr, int* __restrict__ cur,
                                  int N, int E) {
    __shared__ int s[CHUNK];
    __shared__ int p[256];
    int t = threadIdx.x;

    if (t < 256) p[t] = (t < NCHUNK) ? partials[t] : 0;
    __syncthreads();
#pragma unroll
    for (int off = 1; off < 256; off <<= 1) {
        int x = (t < 256 && t >= off) ? p[t - off] : 0;
        __syncthreads();
        if (t < 256) p[t] += x;
        __syncthreads();
    }
    const int chunkOff = (blockIdx.x == 0) ? 0 : p[blockIdx.x - 1];

    int i = blockIdx.x * CHUNK + t;
    int c = (i < N) ? cnt[i] : 0;
    s[t] = c;
    __syncthreads();
#pragma unroll
    for (int off = 1; off < CHUNK; off <<= 1) {
        int x = (t >= off) ? s[t - off] : 0;
        __syncthreads();
        s[t] += x;
        __syncthreads();
    }
    if (i < N) {
        int start = chunkOff + s[t] - c;
        ptr[i] = start;
        cur[i] = start;
        if (i == N - 1) ptr[N] = E;
    }
}

__global__ void scatter_kernel(const int* __restrict__ er, const int* __restrict__ ec,
                               const float* __restrict__ ev,
                               int* __restrict__ cur, int2* __restrict__ csr, int E) {
    int e = blockIdx.x * blockDim.x + threadIdx.x;
    if (e < E) {
        int pos = atomicAdd(&cur[er[e]], 1);
        csr[pos] = make_int2(ec[e], __float_as_int(ev[e]));
    }
}

// ---------------------------------------------------------------------------
// CSR SpMM (R8, unchanged)
// ---------------------------------------------------------------------------
__global__ void csr_spmm_kernel(const int* __restrict__ ptr, const int2* __restrict__ csr,
                                const float* __restrict__ D, float* __restrict__ O, int N) {
    const int lane = threadIdx.x & 31;
    const int g = lane >> 4;
    const int h = lane & 15;
    const int warpId = (blockIdx.x * blockDim.x + threadIdx.x) >> 5;
    const int row = warpId * 2 + g;
    if (row >= N) return;

    const int start = ptr[row];
    const int end   = ptr[row + 1];

    float4 acc = make_float4(0.f, 0.f, 0.f, 0.f);
    int j = start;

    for (; j + 4 <= end; j += 4) {
        const int2 m0 = __ldg(&csr[j]);
        const int2 m1 = __ldg(&csr[j + 1]);
        const int2 m2 = __ldg(&csr[j + 2]);
        const int2 m3 = __ldg(&csr[j + 3]);
        const float4 a0 = *(reinterpret_cast<const float4*>(D + (size_t)m0.x * 64) + h);
        const float4 a1 = *(reinterpret_cast<const float4*>(D + (size_t)m1.x * 64) + h);
        const float4 a2 = *(reinterpret_cast<const float4*>(D + (size_t)m2.x * 64) + h);
        const float4 a3 = *(reinterpret_cast<const float4*>(D + (size_t)m3.x * 64) + h);
        const float v0 = __int_as_float(m0.y), v1 = __int_as_float(m1.y);
        const float v2 = __int_as_float(m2.y), v3 = __int_as_float(m3.y);
        acc.x += v0 * a0.x; acc.y += v0 * a0.y; acc.z += v0 * a0.z; acc.w += v0 * a0.w;
        acc.x += v1 * a1.x; acc.y += v1 * a1.y; acc.z += v1 * a1.z; acc.w += v1 * a1.w;
        acc.x += v2 * a2.x; acc.y += v2 * a2.y; acc.z += v2 * a2.z; acc.w += v2 * a2.w;
        acc.x += v3 * a3.x; acc.y += v3 * a3.y; acc.z += v3 * a3.z; acc.w += v3 * a3.w;
    }
    for (; j < end; j++) {
        const int2 m = __ldg(&csr[j]);
        const float v = __int_as_float(m.y);
        const float4 a = *(reinterpret_cast<const float4*>(D + (size_t)m.x * 64) + h);
        acc.x += v * a.x; acc.y += v * a.y; acc.z += v * a.z; acc.w += v * a.w;
    }

    *(reinterpret_cast<float4*>(O + (size_t)row * 64) + h) = acc;
}

// ---------------------------------------------------------------------------
// tf32 tensor-core GEMM: C[N,64] = act(X[N,K]) @ W[K,64] + b
// 64x64 tile, 256 threads = 8 warps (4 M-warps x 2 N-warps).
// Warp tile 16x32 via 4x m16n8k8 MMA per k-step. fp32 accumulation.
// Smem pads chosen so fragment LDS banks are exact 0..31 permutations:
//   Xs stride 36 -> bank 4*qr + qc (+8k);  Ws stride 72 -> bank 8*qc + qr.
// ---------------------------------------------------------------------------
template<int K, bool RELU>
__global__ void gemm_tf32_kernel(const float* __restrict__ X,
                                 const float* __restrict__ W,
                                 const float* __restrict__ b,
                                 float* __restrict__ C, int N) {
    constexpr int BK = 32;
    __shared__ float Xs[64][36];
    __shared__ float Ws[BK][72];
    __shared__ float bsm[64];

    const int tid  = threadIdx.x;
    const int lane = tid & 31;
    const int warp = tid >> 5;
    const int mw = warp & 3;          // M-warp: rows mw*16 .. +15
    const int nw = warp >> 2;         // N-warp: cols nw*32 .. +31
    const int qr = lane >> 2;         // 0..7
    const int qc = lane & 3;          // 0..3
    const int nodeBase = blockIdx.x * 64;

    if (tid < 64) bsm[tid] = b[tid];

    float4 acc[4];
#pragma unroll
    for (int s = 0; s < 4; s++) acc[s] = make_float4(0.f, 0.f, 0.f, 0.f);

    for (int kc = 0; kc < K; kc += BK) {
        // X tile: 64 rows x 32 cols = 512 float4, 2 per thread (coalesced).
#pragma unroll
        for (int t = 0; t < 2; t++) {
            int idx = tid + t * 256;
            int r   = idx >> 3;
            int c4  = idx & 7;
            int node = nodeBase + r;
            float4 xv = make_float4(0.f, 0.f, 0.f, 0.f);
            if (node < N)
                xv = *reinterpret_cast<const float4*>(X + (size_t)node * K + kc + c4 * 4);
            if (RELU) {
                xv.x = fmaxf(xv.x, 0.f); xv.y = fmaxf(xv.y, 0.f);
                xv.z = fmaxf(xv.z, 0.f); xv.w = fmaxf(xv.w, 0.f);
            }
            xv.x = to_tf32(xv.x); xv.y = to_tf32(xv.y);
            xv.z = to_tf32(xv.z); xv.w = to_tf32(xv.w);
            *reinterpret_cast<float4*>(&Xs[r][c4 * 4]) = xv;
        }
        // W chunk: 32 rows x 64 cols = 512 float4, 2 per thread.
#pragma unroll
        for (int t = 0; t < 2; t++) {
            int idx = tid + t * 256;
            int r   = idx >> 4;
            int c4  = idx & 15;
            float4 wv = *reinterpret_cast<const float4*>(W + (size_t)(kc + r) * 64 + c4 * 4);
            wv.x = to_tf32(wv.x); wv.y = to_tf32(wv.y);
            wv.z = to_tf32(wv.z); wv.w = to_tf32(wv.w);
            *reinterpret_cast<float4*>(&Ws[r][c4 * 4]) = wv;
        }
        __syncthreads();

#pragma unroll
        for (int kk = 0; kk < BK / 8; kk++) {
            const int k0 = kk * 8;
            // A fragment (16x8, row-major)
            const unsigned a0 = __float_as_uint(Xs[mw * 16 + qr    ][k0 + qc    ]);
            const unsigned a1 = __float_as_uint(Xs[mw * 16 + qr + 8][k0 + qc    ]);
            const unsigned a2 = __float_as_uint(Xs[mw * 16 + qr    ][k0 + qc + 4]);
            const unsigned a3 = __float_as_uint(Xs[mw * 16 + qr + 8][k0 + qc + 4]);
#pragma unroll
            for (int s = 0; s < 4; s++) {
                const int n0 = nw * 32 + s * 8;
                const unsigned b0 = __float_as_uint(Ws[k0 + qc    ][n0 + qr]);
                const unsigned b1 = __float_as_uint(Ws[k0 + qc + 4][n0 + qr]);
                mma_tf32(acc[s], a0, a1, a2, a3, b0, b1);
            }
        }
        __syncthreads();
    }

    // Epilogue: add bias, store. c0,c1 -> (row0, col0..1), c2,c3 -> (row0+8, ...)
    const int row0 = nodeBase + mw * 16 + qr;
    const int row1 = row0 + 8;
#pragma unroll
    for (int s = 0; s < 4; s++) {
        const int col0 = nw * 32 + s * 8 + qc * 2;
        const float bb0 = bsm[col0], bb1 = bsm[col0 + 1];
        if (row0 < N)
            *reinterpret_cast<float2*>(C + (size_t)row0 * 64 + col0) =
                make_float2(acc[s].x + bb0, acc[s].y + bb1);
        if (row1 < N)
            *reinterpret_cast<float2*>(C + (size_t)row1 * 64 + col0) =
                make_float2(acc[s].z + bb0, acc[s].w + bb1);
    }
}

// ---------------------------------------------------------------------------
// Classifier (R8, unchanged): out = log_softmax(H @ Wc + bc), warp per node.
// ---------------------------------------------------------------------------
__global__ void classifier_kernel(const float* __restrict__ H,
                                  const float* __restrict__ Wc,
                                  const float* __restrict__ bc,
                                  float* __restrict__ out, int N) {
    __shared__ float2 Wp[64][32];
    __shared__ float bs[40];
    __shared__ float hs[8][64];

    const int tid  = threadIdx.x;
    const int lane = tid & 31;
    const int warp = tid >> 5;

    for (int i = tid; i < 64 * 32; i += 256) {
        int k = i >> 5, l = i & 31;
        float w0 = Wc[k * 40 + l];
        float w1 = (l < 8) ? Wc[k * 40 + 32 + l] : 0.f;
        Wp[k][l] = make_float2(w0, w1);
    }
    if (tid < 40) bs[tid] = bc[tid];
    __syncthreads();

    for (int it = 0; it < 4; it++) {
        const int node = blockIdx.x * 32 + it * 8 + warp;
        if (node < N) {
            __syncwarp();
            hs[warp][lane]      = H[(size_t)node * 64 + lane];
            hs[warp][lane + 32] = H[(size_t)node * 64 + lane + 32];
            __syncwarp();

            float v0 = bs[lane];
            float v1 = (lane < 8) ? bs[32 + lane] : 0.f;
#pragma unroll
            for (int k = 0; k < 64; k++) {
                const float h = hs[warp][k];
                const float2 w = Wp[k][lane];
                v0 += h * w.x;
                v1 += h * w.y;
            }

            float m = (lane < 8) ? fmaxf(v0, v1) : v0;
#pragma unroll
            for (int off = 16; off; off >>= 1)
                m = fmaxf(m, __shfl_xor_sync(0xffffffffu, m, off));
            float s = expf(v0 - m) + ((lane < 8) ? expf(v1 - m) : 0.f);
#pragma unroll
            for (int off = 16; off; off >>= 1)
                s += __shfl_xor_sync(0xffffffffu, s, off);
            const float lse = m + logf(s);

            out[(size_t)node * 40 + lane] = v0 - lse;
            if (lane < 8)
                out[(size_t)node * 40 + 32 + lane] = v1 - lse;
        }
    }
}

// ---------------------------------------------------------------------------
// launch (single stream, R8 structure; GEMMs tensorized)
// ---------------------------------------------------------------------------
extern "C" void kernel_launch(void* const* d_in, const int* in_sizes, int n_in,
                              void* d_out, int out_size) {
    const float* x  = (const float*)d_in[0];
    const int*   er = (const int*)  d_in[1];
    const int*   ec = (const int*)  d_in[2];
    const float* ev = (const float*)d_in[3];
    const float* W1 = (const float*)d_in[4];
    const float* b1 = (const float*)d_in[5];
    const float* W2 = (const float*)d_in[6];
    const float* b2 = (const float*)d_in[7];
    const float* Wc = (const float*)d_in[8];
    const float* bc = (const float*)d_in[9];
    float* out = (float*)d_out;

    const int N = in_sizes[0] / IN_DIM;   // 100000
    const int E = in_sizes[1];            // 1600000

    void *pA_, *pB_, *pCnt_, *pPtr_, *pPar_, *pCsr_;
    cudaGetSymbolAddress(&pA_, g_A);
    cudaGetSymbolAddress(&pB_, g_B);
    cudaGetSymbolAddress(&pCnt_, g_cnt);
    cudaGetSymbolAddress(&pPtr_, g_ptr);
    cudaGetSymbolAddress(&pPar_, g_partials);
    cudaGetSymbolAddress(&pCsr_, g_csr);
    float* A   = (float*)pA_;
    float* B   = (float*)pB_;
    int*   cnt = (int*)pCnt_;
    int*   ptr = (int*)pPtr_;
    int*   par = (int*)pPar_;
    int2*  csr = (int2*)pCsr_;

    const int gemmBlocks = (N + 63) / 64;
    const int eBlocks    = (E + 255) / 256;
    const int spmmBlocks = (N + 15) / 16;
    const int clsBlocks  = (N + 31) / 32;

    // --- CSR build ---
    zero_int_kernel<<<(N + 255) / 256, 256>>>(cnt, N);
    hist_kernel<<<eBlocks, 256>>>(er, cnt, E);
    chunk_reduce_kernel<<<NCHUNK, CHUNK>>>(cnt, par, N);
    block_scan_kernel<<<NCHUNK, CHUNK>>>(cnt, par, ptr, cnt /*cursor*/, N, E);
    scatter_kernel<<<eBlocks, 256>>>(er, ec, ev, cnt, csr, E);

    // --- Layer 1 ---
    gemm_tf32_kernel<IN_DIM, false><<<gemmBlocks, 256>>>(x, W1, b1, A, N);
    csr_spmm_kernel<<<spmmBlocks, 256>>>(ptr, csr, A, B, N);

    // --- Layer 2 (relu fused into GEMM read) ---
    gemm_tf32_kernel<HID, true><<<gemmBlocks, 256>>>(B, W2, b2, A, N);
    csr_spmm_kernel<<<spmmBlocks, 256>>>(ptr, csr, A, B, N);

    // --- Classifier + log-softmax ---
    classifier_kernel<<<clsBlocks, 256>>>(B, Wc, bc, out, N);
}

// round 10
// speedup vs baseline: 1.2873x; 1.2873x over previous
#include <cuda_runtime.h>
#include <cuda_bf16.h>
#include <math.h>

#define N_NODES 100000
#define IN_DIM  128
#define HID     64
#define NCLS    40
#define N_EDGES 1600000
#define CHUNK   512
#define NCHUNK  ((N_NODES + CHUNK - 1) / CHUNK)   // 196

// Scratch (__device__ globals per alloc-free rule)
__device__ float g_A[(size_t)N_NODES * HID];
__device__ float g_B[(size_t)N_NODES * HID];
__device__ int   g_cnt[N_NODES];
__device__ int   g_ptr[N_NODES + 1];
__device__ int   g_partials[NCHUNK];
__device__ int2  g_csr[N_EDGES];

// ---------------------------------------------------------------------------
// CSR construction (R8, unchanged)
// ---------------------------------------------------------------------------
__global__ void zero_int_kernel(int* __restrict__ p, int n) {
    int i = blockIdx.x * blockDim.x + threadIdx.x;
    if (i < n) p[i] = 0;
}

__global__ void hist_kernel(const int* __restrict__ er, int* __restrict__ cnt, int E) {
    int e = blockIdx.x * blockDim.x + threadIdx.x;
    if (e < E) atomicAdd(&cnt[er[e]], 1);
}

__global__ void chunk_reduce_kernel(const int* __restrict__ cnt, int* __restrict__ partials, int N) {
    __shared__ int s[CHUNK];
    int t = threadIdx.x;
    int i = blockIdx.x * CHUNK + t;
    s[t] = (i < N) ? cnt[i] : 0;
    __syncthreads();
    for (int off = CHUNK / 2; off > 0; off >>= 1) {
        if (t < off) s[t] += s[t + off];
        __syncthreads();
    }
    if (t == 0) partials[blockIdx.x] = s[0];
}

__global__ void block_scan_kernel(const int* __restrict__ cnt,
                                  const int* __restrict__ partials,
                                  int* __restrict__ ptr, int* __restrict__ cur,
                                  int N, int E) {
    __shared__ int s[CHUNK];
    __shared__ int p[256];
    int t = threadIdx.x;

    if (t < 256) p[t] = (t < NCHUNK) ? partials[t] : 0;
    __syncthreads();
#pragma unroll
    for (int off = 1; off < 256; off <<= 1) {
        int x = (t < 256 && t >= off) ? p[t - off] : 0;
        __syncthreads();
        if (t < 256) p[t] += x;
        __syncthreads();
    }
    const int chunkOff = (blockIdx.x == 0) ? 0 : p[blockIdx.x - 1];

    int i = blockIdx.x * CHUNK + t;
    int c = (i < N) ? cnt[i] : 0;
    s[t] = c;
    __syncthreads();
#pragma unroll
    for (int off = 1; off < CHUNK; off <<= 1) {
        int x = (t >= off) ? s[t - off] : 0;
        __syncthreads();
        s[t] += x;
        __syncthreads();
    }
    if (i < N) {
        int start = chunkOff + s[t] - c;
        ptr[i] = start;
        cur[i] = start;
        if (i == N - 1) ptr[N] = E;
    }
}

__global__ void scatter_kernel(const int* __restrict__ er, const int* __restrict__ ec,
                               const float* __restrict__ ev,
                               int* __restrict__ cur, int2* __restrict__ csr, int E) {
    int e = blockIdx.x * blockDim.x + threadIdx.x;
    if (e < E) {
        int pos = atomicAdd(&cur[er[e]], 1);
        csr[pos] = make_int2(ec[e], __float_as_int(ev[e]));
    }
}

// ---------------------------------------------------------------------------
// CSR SpMM (R8, unchanged) — used for layer 1
// ---------------------------------------------------------------------------
__global__ void csr_spmm_kernel(const int* __restrict__ ptr, const int2* __restrict__ csr,
                                const float* __restrict__ D, float* __restrict__ O, int N) {
    const int lane = threadIdx.x & 31;
    const int g = lane >> 4;
    const int h = lane & 15;
    const int warpId = (blockIdx.x * blockDim.x + threadIdx.x) >> 5;
    const int row = warpId * 2 + g;
    if (row >= N) return;

    const int start = ptr[row];
    const int end   = ptr[row + 1];

    float4 acc = make_float4(0.f, 0.f, 0.f, 0.f);
    int j = start;

    for (; j + 4 <= end; j += 4) {
        const int2 m0 = __ldg(&csr[j]);
        const int2 m1 = __ldg(&csr[j + 1]);
        const int2 m2 = __ldg(&csr[j + 2]);
        const int2 m3 = __ldg(&csr[j + 3]);
        const float4 a0 = *(reinterpret_cast<const float4*>(D + (size_t)m0.x * 64) + h);
        const float4 a1 = *(reinterpret_cast<const float4*>(D + (size_t)m1.x * 64) + h);
        const float4 a2 = *(reinterpret_cast<const float4*>(D + (size_t)m2.x * 64) + h);
        const float4 a3 = *(reinterpret_cast<const float4*>(D + (size_t)m3.x * 64) + h);
        const float v0 = __int_as_float(m0.y), v1 = __int_as_float(m1.y);
        const float v2 = __int_as_float(m2.y), v3 = __int_as_float(m3.y);
        acc.x += v0 * a0.x; acc.y += v0 * a0.y; acc.z += v0 * a0.z; acc.w += v0 * a0.w;
        acc.x += v1 * a1.x; acc.y += v1 * a1.y; acc.z += v1 * a1.z; acc.w += v1 * a1.w;
        acc.x += v2 * a2.x; acc.y += v2 * a2.y; acc.z += v2 * a2.z; acc.w += v2 * a2.w;
        acc.x += v3 * a3.x; acc.y += v3 * a3.y; acc.z += v3 * a3.z; acc.w += v3 * a3.w;
    }
    for (; j < end; j++) {
        const int2 m = __ldg(&csr[j]);
        const float v = __int_as_float(m.y);
        const float4 a = *(reinterpret_cast<const float4*>(D + (size_t)m.x * 64) + h);
        acc.x += v * a.x; acc.y += v * a.y; acc.z += v * a.z; acc.w += v * a.w;
    }

    *(reinterpret_cast<float4*>(O + (size_t)row * 64) + h) = acc;
}

// ---------------------------------------------------------------------------
// Fused SpMM2 + classifier: h2 rows stay in smem; out = log_softmax(h2@Wc+bc).
// 256 threads = 8 warps = 16 rows/block (N divisible by 16 -> no partials).
// Stage 1: identical gather math to csr_spmm. Stage 2: identical classifier
// math (warp-per-node, float2-packed Wc). No h2 gmem round-trip.
// ---------------------------------------------------------------------------
__global__ void spmm_classifier_kernel(const int* __restrict__ ptr,
                                       const int2* __restrict__ csr,
                                       const float* __restrict__ D,
                                       const float* __restrict__ Wc,
                                       const float* __restrict__ bc,
                                       float* __restrict__ out, int N) {
    __shared__ float  hs[16][64];
    __shared__ float2 Wp[64][32];
    __shared__ float  bs[40];

    const int tid  = threadIdx.x;
    const int lane = tid & 31;
    const int warp = tid >> 5;
    const int g = lane >> 4;
    const int h = lane & 15;

    // Load packed Wc + bias (overlaps with gather issue below via ILP).
    for (int i = tid; i < 64 * 32; i += 256) {
        int k = i >> 5, l = i & 31;
        float w0 = Wc[k * 40 + l];
        float w1 = (l < 8) ? Wc[k * 40 + 32 + l] : 0.f;
        Wp[k][l] = make_float2(w0, w1);
    }
    if (tid < 40) bs[tid] = bc[tid];

    // ---- Stage 1: SpMM for this block's 16 rows ----
    const int localRow = warp * 2 + g;             // 0..15
    const int row = blockIdx.x * 16 + localRow;

    if (row < N) {
        const int start = ptr[row];
        const int end   = ptr[row + 1];

        float4 acc = make_float4(0.f, 0.f, 0.f, 0.f);
        int j = start;

        for (; j + 4 <= end; j += 4) {
            const int2 m0 = __ldg(&csr[j]);
            const int2 m1 = __ldg(&csr[j + 1]);
            const int2 m2 = __ldg(&csr[j + 2]);
            const int2 m3 = __ldg(&csr[j + 3]);
            const float4 a0 = *(reinterpret_cast<const float4*>(D + (size_t)m0.x * 64) + h);
            const float4 a1 = *(reinterpret_cast<const float4*>(D + (size_t)m1.x * 64) + h);
            const float4 a2 = *(reinterpret_cast<const float4*>(D + (size_t)m2.x * 64) + h);
            const float4 a3 = *(reinterpret_cast<const float4*>(D + (size_t)m3.x * 64) + h);
            const float v0 = __int_as_float(m0.y), v1 = __int_as_float(m1.y);
            const float v2 = __int_as_float(m2.y), v3 = __int_as_float(m3.y);
            acc.x += v0 * a0.x; acc.y += v0 * a0.y; acc.z += v0 * a0.z; acc.w += v0 * a0.w;
            acc.x += v1 * a1.x; acc.y += v1 * a1.y; acc.z += v1 * a1.z; acc.w += v1 * a1.w;
            acc.x += v2 * a2.x; acc.y += v2 * a2.y; acc.z += v2 * a2.z; acc.w += v2 * a2.w;
            acc.x += v3 * a3.x; acc.y += v3 * a3.y; acc.z += v3 * a3.z; acc.w += v3 * a3.w;
        }
        for (; j < end; j++) {
            const int2 m = __ldg(&csr[j]);
            const float v = __int_as_float(m.y);
            const float4 a = *(reinterpret_cast<const float4*>(D + (size_t)m.x * 64) + h);
            acc.x += v * a.x; acc.y += v * a.y; acc.z += v * a.z; acc.w += v * a.w;
        }

        *reinterpret_cast<float4*>(&hs[localRow][h * 4]) = acc;
    }
    __syncthreads();

    // ---- Stage 2: classifier, warp-per-node, 2 nodes per warp ----
#pragma unroll
    for (int it = 0; it < 2; it++) {
        const int r = warp * 2 + it;               // 0..15
        const int node = blockIdx.x * 16 + r;
        if (node < N) {
            float v0 = bs[lane];
            float v1 = (lane < 8) ? bs[32 + lane] : 0.f;
#pragma unroll
            for (int k = 0; k < 64; k++) {
                const float hv = hs[r][k];
                const float2 w = Wp[k][lane];
                v0 += hv * w.x;
                v1 += hv * w.y;
            }

            float m = (lane < 8) ? fmaxf(v0, v1) : v0;
#pragma unroll
            for (int off = 16; off; off >>= 1)
                m = fmaxf(m, __shfl_xor_sync(0xffffffffu, m, off));
            float s = expf(v0 - m) + ((lane < 8) ? expf(v1 - m) : 0.f);
#pragma unroll
            for (int off = 16; off; off >>= 1)
                s += __shfl_xor_sync(0xffffffffu, s, off);
            const float lse = m + logf(s);

            out[(size_t)node * 40 + lane] = v0 - lse;
            if (lane < 8)
                out[(size_t)node * 40 + 32 + lane] = v1 - lse;
        }
    }
}

// ---------------------------------------------------------------------------
// Tiled GEMM (R8 scalar, conflict-free smem): C = act(X)@W + b
// ---------------------------------------------------------------------------
template<int K, bool RELU>
__global__ void gemm64_kernel(const float* __restrict__ X,
                              const float* __restrict__ W,
                              const float* __restrict__ b,
                              float* __restrict__ C, int N) {
    constexpr int BK = 32;
    __shared__ float Xs[64][BK + 1];
    __shared__ float Ws[BK][64];

    const int tid = threadIdx.x;
    const int tx = tid & 15;
    const int ty = tid >> 4;
    const int nodeBase = blockIdx.x * 64;

    float acc[4][4];
    const float4 bv = *reinterpret_cast<const float4*>(b + tx * 4);
#pragma unroll
    for (int i = 0; i < 4; i++) {
        acc[i][0] = bv.x; acc[i][1] = bv.y; acc[i][2] = bv.z; acc[i][3] = bv.w;
    }

    for (int kc = 0; kc < K; kc += BK) {
#pragma unroll
        for (int t = 0; t < 2; t++) {
            int idx = tid + t * 256;
            int r   = idx >> 3;
            int c4  = idx & 7;
            int node = nodeBase + r;
            float4 xv = make_float4(0.f, 0.f, 0.f, 0.f);
            if (node < N)
                xv = *reinterpret_cast<const float4*>(X + (size_t)node * K + kc + c4 * 4);
            if (RELU) {
                xv.x = fmaxf(xv.x, 0.f); xv.y = fmaxf(xv.y, 0.f);
                xv.z = fmaxf(xv.z, 0.f); xv.w = fmaxf(xv.w, 0.f);
            }
            Xs[r][c4 * 4 + 0] = xv.x;
            Xs[r][c4 * 4 + 1] = xv.y;
            Xs[r][c4 * 4 + 2] = xv.z;
            Xs[r][c4 * 4 + 3] = xv.w;
        }
#pragma unroll
        for (int t = 0; t < 2; t++) {
            int idx = tid + t * 256;
            int r   = idx >> 4;
            int c4  = idx & 15;
            *reinterpret_cast<float4*>(&Ws[r][c4 * 4]) =
                *reinterpret_cast<const float4*>(W + (size_t)(kc + r) * 64 + c4 * 4);
        }
        __syncthreads();

#pragma unroll
        for (int kk = 0; kk < BK; kk++) {
            const float4 wv = *reinterpret_cast<const float4*>(&Ws[kk][tx * 4]);
            float xv[4];
#pragma unroll
            for (int i = 0; i < 4; i++) xv[i] = Xs[ty * 4 + i][kk];
#pragma unroll
            for (int i = 0; i < 4; i++) {
                acc[i][0] += xv[i] * wv.x;
                acc[i][1] += xv[i] * wv.y;
                acc[i][2] += xv[i] * wv.z;
                acc[i][3] += xv[i] * wv.w;
            }
        }
        __syncthreads();
    }

#pragma unroll
    for (int i = 0; i < 4; i++) {
        int node = nodeBase + ty * 4 + i;
        if (node < N) {
            float4 o = make_float4(acc[i][0], acc[i][1], acc[i][2], acc[i][3]);
            *reinterpret_cast<float4*>(C + (size_t)node * 64 + tx * 4) = o;
        }
    }
}

// ---------------------------------------------------------------------------
// launch (single stream)
// ---------------------------------------------------------------------------
extern "C" void kernel_launch(void* const* d_in, const int* in_sizes, int n_in,
                              void* d_out, int out_size) {
    const float* x  = (const float*)d_in[0];
    const int*   er = (const int*)  d_in[1];
    const int*   ec = (const int*)  d_in[2];
    const float* ev = (const float*)d_in[3];
    const float* W1 = (const float*)d_in[4];
    const float* b1 = (const float*)d_in[5];
    const float* W2 = (const float*)d_in[6];
    const float* b2 = (const float*)d_in[7];
    const float* Wc = (const float*)d_in[8];
    const float* bc = (const float*)d_in[9];
    float* out = (float*)d_out;

    const int N = in_sizes[0] / IN_DIM;   // 100000
    const int E = in_sizes[1];            // 1600000

    void *pA_, *pB_, *pCnt_, *pPtr_, *pPar_, *pCsr_;
    cudaGetSymbolAddress(&pA_, g_A);
    cudaGetSymbolAddress(&pB_, g_B);
    cudaGetSymbolAddress(&pCnt_, g_cnt);
    cudaGetSymbolAddress(&pPtr_, g_ptr);
    cudaGetSymbolAddress(&pPar_, g_partials);
    cudaGetSymbolAddress(&pCsr_, g_csr);
    float* A   = (float*)pA_;
    float* B   = (float*)pB_;
    int*   cnt = (int*)pCnt_;
    int*   ptr = (int*)pPtr_;
    int*   par = (int*)pPar_;
    int2*  csr = (int2*)pCsr_;

    const int gemmBlocks = (N + 63) / 64;
    const int eBlocks    = (E + 255) / 256;
    const int spmmBlocks = (N + 15) / 16;

    // --- CSR build ---
    zero_int_kernel<<<(N + 255) / 256, 256>>>(cnt, N);
    hist_kernel<<<eBlocks, 256>>>(er, cnt, E);
    chunk_reduce_kernel<<<NCHUNK, CHUNK>>>(cnt, par, N);
    block_scan_kernel<<<NCHUNK, CHUNK>>>(cnt, par, ptr, cnt /*cursor*/, N, E);
    scatter_kernel<<<eBlocks, 256>>>(er, ec, ev, cnt, csr, E);

    // --- Layer 1 ---
    gemm64_kernel<IN_DIM, false><<<gemmBlocks, 256>>>(x, W1, b1, A, N);
    csr_spmm_kernel<<<spmmBlocks, 256>>>(ptr, csr, A, B, N);

    // --- Layer 2 (relu fused into GEMM read) ---
    gemm64_kernel<HID, true><<<gemmBlocks, 256>>>(B, W2, b2, A, N);

    // --- SpMM2 + classifier fused (no h2 round-trip) ---
    spmm_classifier_kernel<<<spmmBlocks, 256>>>(ptr, csr, A, Wc, bc, out, N);
}